// round 8
// baseline (speedup 1.0000x reference)
#include <cuda_runtime.h>
#include <cuda_bf16.h>
#include <cstdint>

// ===========================================================================
// TrainableTree: out[n] = a(x_n) * ( sin(Wt x_n + bt) . w_eff + c )
// Tree after sin() is linear with OUT=1 -> collapses to (w_eff[64], c).
// SINGLE fused kernel: blocks 0-15 compose (w_eff,c) then join the main work;
// all blocks overlap B-tile setup with compose and sync via a device flag
// (all blocks co-resident: grid <= 148 SMs x 3 blocks).
// Main loop: HMMA (bf16 hi/lo split, fp32 accum) -> MUFU sin -> dot -> out.
// ===========================================================================

__device__ float g_part[16][64];   // per-leaf partials of w_eff
__device__ float c_part[16];       // per-leaf partials of c
__device__ int   g_ready;          // compose-done counter (reset each launch)
__device__ int   g_exit;           // block-exit counter for the reset

// ---------------- helpers ----------------
__device__ __forceinline__ uint32_t bfpk(float lo, float hi) {
    uint32_t d;
    asm("cvt.rn.bf16x2.f32 %0, %1, %2;" : "=r"(d) : "f"(hi), "f"(lo));
    return d;   // lower 16 = bf16(lo), upper 16 = bf16(hi)
}
__device__ __forceinline__ float bflo(uint32_t p) { return __uint_as_float(p << 16); }
__device__ __forceinline__ float bfhi(uint32_t p) { return __uint_as_float(p & 0xffff0000u); }

__global__ void __launch_bounds__(256, 3)
fused_kernel(const float* __restrict__ x,
             const float* __restrict__ Wt, const float* __restrict__ bt,
             const float* __restrict__ Wleaf, const float* __restrict__ bleaf,
             const float* __restrict__ W3, const float* __restrict__ b3,
             const float* __restrict__ W2, const float* __restrict__ b2,
             const float* __restrict__ W1, const float* __restrict__ b1,
             const float* __restrict__ Wr, const float* __restrict__ br,
             float* __restrict__ out, int N, int n_chunks) {
    __shared__ uint32_t sB[64][18];       // [out][k-pair], 72B rows
    __shared__ uint32_t sA[8][16][20];    // per warp: 16 rows x 80B
    __shared__ float sWeff[64];
    __shared__ float sC[1];

    const int t = threadIdx.x;
    const int wid = t >> 5, lane = t & 31;
    const int c = lane & 3, g = lane >> 2;

    // =====================================================================
    // Compose (blocks 0-15): weights register-resident, one latency round.
    // =====================================================================
    if (blockIdx.x < 16) {
        __shared__ float sGr[64], sG1[64], sG2[64], sG3[64];
        __shared__ float red[4][64];
        __shared__ float cp[64];

        const int k = blockIdx.x;
        const int o = t & 63, q = t >> 6;   // q in 0..3
        const int p0 = q * 16;

        const float* W1n = W1 + (k >> 3) * 4096;
        const float* W2n = W2 + (k >> 2) * 4096;
        const float* W3n = W3 + (k >> 1) * 4096;
        const float* WLn = Wleaf + k * 4096;
        float w1r[16], w2r[16], w3r[16], wlr[16];
        #pragma unroll
        for (int i = 0; i < 16; i++) w1r[i] = W1n[(p0 + i) * 64 + o];
        #pragma unroll
        for (int i = 0; i < 16; i++) w2r[i] = W2n[(p0 + i) * 64 + o];
        #pragma unroll
        for (int i = 0; i < 16; i++) w3r[i] = W3n[(p0 + i) * 64 + o];
        #pragma unroll
        for (int i = 0; i < 16; i++) wlr[i] = WLn[(p0 + i) * 64 + o];

        const float blf = bleaf[k * 64 + o];
        const float b3v = ((k & 1) == 0) ? b3[(k >> 1) * 64 + o] : 0.f;
        const float b2v = ((k & 3) == 0) ? b2[(k >> 2) * 64 + o] : 0.f;
        const float b1v = (k == 0) ? (b1[o] + b1[64 + o]) : 0.f;

        if (t < 64) sGr[t] = Wr[t];
        __syncthreads();

        {
            float s = 0.f;
            #pragma unroll
            for (int i = 0; i < 16; i++) s = fmaf(w1r[i], sGr[p0 + i], s);
            red[q][o] = s;
        }
        __syncthreads();
        if (t < 64) sG1[t] = red[0][t] + red[1][t] + red[2][t] + red[3][t];
        __syncthreads();
        {
            float s = 0.f;
            #pragma unroll
            for (int i = 0; i < 16; i++) s = fmaf(w2r[i], sG1[p0 + i], s);
            red[q][o] = s;
        }
        __syncthreads();
        if (t < 64) sG2[t] = red[0][t] + red[1][t] + red[2][t] + red[3][t];
        __syncthreads();
        {
            float s = 0.f;
            #pragma unroll
            for (int i = 0; i < 16; i++) s = fmaf(w3r[i], sG2[p0 + i], s);
            red[q][o] = s;
        }
        __syncthreads();
        if (t < 64) sG3[t] = red[0][t] + red[1][t] + red[2][t] + red[3][t];
        __syncthreads();
        {
            float s = 0.f;
            #pragma unroll
            for (int i = 0; i < 16; i++) s = fmaf(wlr[i], sG3[p0 + i], s);
            red[q][o] = s;
        }
        __syncthreads();
        if (t < 64) g_part[k][t] = red[0][t] + red[1][t] + red[2][t] + red[3][t];

        if (t < 64) {
            float s = sG3[o] * blf;
            s = fmaf(sG2[o], b3v, s);
            s = fmaf(sG1[o], b2v, s);
            s = fmaf(sGr[o], b1v, s);
            cp[o] = s;
        }
        __syncthreads();
        if (t == 0) {
            float s = (k == 0) ? br[0] : 0.f;
            #pragma unroll 8
            for (int i = 0; i < 64; i++) s += cp[i];
            c_part[k] = s;
        }
        __threadfence();          // release g_part/c_part
        __syncthreads();
        if (t == 0) atomicAdd(&g_ready, 1);
    }

    // =====================================================================
    // B-tile build (independent of compose; overlaps the spin below)
    // =====================================================================
    if (t < 64) {
        const float2* wr = (const float2*)(Wt + t * 10);
        uint32_t H[5], L[5];
        #pragma unroll
        for (int j = 0; j < 5; j++) {
            const float2 v = wr[j];
            H[j] = bfpk(v.x, v.y);
            L[j] = bfpk(v.x - bflo(H[j]), v.y - bfhi(H[j]));
        }
        const float bv = bt[t];
        const uint32_t bh = bfpk(bv, 0.f);
        const uint32_t bp = bfpk(bv, bv - bflo(bh));   // {bt_hi, bt_lo}
        #pragma unroll
        for (int j = 0; j < 5; j++) {
            sB[t][j]      = H[j];   // k 0-9  : W_hi
            sB[t][5 + j]  = H[j];   // k 10-19: W_hi
            sB[t][10 + j] = L[j];   // k 20-29: W_lo
        }
        sB[t][15] = bp;             // k 30,31: bt_hi, bt_lo
        sB[t][16] = 0u; sB[t][17] = 0u;
    }
    __syncthreads();

    // B fragments into registers (loop-invariant)
    uint32_t bf0[8][2], bf1[8][2];
    #pragma unroll
    for (int nt = 0; nt < 8; nt++) {
        const int row = 8 * nt + g;
        #pragma unroll
        for (int kc = 0; kc < 2; kc++) {
            bf0[nt][kc] = sB[row][kc * 8 + c];
            bf1[nt][kc] = sB[row][kc * 8 + 4 + c];
        }
    }

    // ---- wait for compose, then reduce w_eff / c ----
    if (t == 0) {
        while (*(volatile int*)&g_ready < 16) __nanosleep(64);
        __threadfence();          // acquire
    }
    __syncthreads();
    if (t < 64) {
        float s = 0.f;
        #pragma unroll
        for (int k = 0; k < 16; k++) s += g_part[k][t];
        sWeff[t] = s;
    }
    if (t == 64) {
        float s = 0.f;
        #pragma unroll
        for (int k = 0; k < 16; k++) s += c_part[k];
        sC[0] = s;
    }
    __syncthreads();
    const float cv = sC[0];

    // =====================================================================
    // Main loop: 16 samples per warp-iteration.
    // =====================================================================
    const int s16 = lane & 15;
    const int lm_sub = lane >> 3, lm_r = lane & 7;
    const int lm_row = lm_r + 8 * (lm_sub & 1);
    const uint32_t lm_base =
        (uint32_t)__cvta_generic_to_shared(&sA[wid][lm_row][0]) + (lm_sub >> 1) * 16;

    const int wglobal = blockIdx.x * 8 + wid;
    const int wstride = gridDim.x * 8;
    const int xstep = wstride * 160;       // floats per stride step
    const int ostep = wstride * 16;

    const float* xp = x + (size_t)(wglobal * 16 + s16) * 10;
    float* outp = out + wglobal * 16;

    // prologue: first chunk's x (N is a multiple of 16; ch<n_chunks => in range)
    float xv[10];
    if (wglobal < n_chunks) {
        const float2* p = (const float2*)xp;
        #pragma unroll
        for (int i = 0; i < 5; i++) { float2 v = p[i]; xv[2*i] = v.x; xv[2*i+1] = v.y; }
    }

    for (int ch = wglobal; ch < n_chunks; ch += wstride) {
        // envelope
        float env = fmaf(xv[0], xv[0], -1.f);
        #pragma unroll
        for (int d = 1; d < 10; d++) env *= fmaf(xv[d], xv[d], -1.f);
        env = env * rsqrtf(fmaf(env, env, 1000.f));

        // stage A row (2 lanes per sample; lane<16: k-pairs 0-7, else 8-15)
        uint32_t H[5];
        #pragma unroll
        for (int j = 0; j < 5; j++) H[j] = bfpk(xv[2 * j], xv[2 * j + 1]);
        uint32_t* arow = sA[wid][s16];
        if (lane < 16) {
            const uint32_t L0 = bfpk(xv[0] - bflo(H[0]), xv[1] - bfhi(H[0]));
            const uint32_t L1 = bfpk(xv[2] - bflo(H[1]), xv[3] - bfhi(H[1]));
            const uint32_t L2 = bfpk(xv[4] - bflo(H[2]), xv[5] - bfhi(H[2]));
            *(uint4*)&arow[0] = make_uint4(H[0], H[1], H[2], H[3]);
            *(uint4*)&arow[4] = make_uint4(H[4], L0, L1, L2);
        } else {
            const uint32_t L3 = bfpk(xv[6] - bflo(H[3]), xv[7] - bfhi(H[3]));
            const uint32_t L4 = bfpk(xv[8] - bflo(H[4]), xv[9] - bfhi(H[4]));
            *(uint4*)&arow[8]  = make_uint4(L3, L4, H[0], H[1]);
            *(uint4*)&arow[12] = make_uint4(H[2], H[3], H[4], 0x3f803f80u); // ones
        }
        __syncwarp();

        uint32_t a0[4], a1[4];
        asm volatile("ldmatrix.sync.aligned.m8n8.x4.shared.b16 {%0,%1,%2,%3}, [%4];"
                     : "=r"(a0[0]), "=r"(a0[1]), "=r"(a0[2]), "=r"(a0[3])
                     : "r"(lm_base));
        asm volatile("ldmatrix.sync.aligned.m8n8.x4.shared.b16 {%0,%1,%2,%3}, [%4];"
                     : "=r"(a1[0]), "=r"(a1[1]), "=r"(a1[2]), "=r"(a1[3])
                     : "r"(lm_base + 32));

        // prefetch next chunk's x (hidden under MMA + sin + dot)
        xp += xstep;
        if (ch + wstride < n_chunks) {
            const float2* p = (const float2*)xp;
            #pragma unroll
            for (int i = 0; i < 5; i++) { float2 v = p[i]; xv[2*i] = v.x; xv[2*i+1] = v.y; }
        }

        float accA = 0.f, accB = 0.f;
        #pragma unroll
        for (int nt = 0; nt < 8; nt++) {
            float d0 = 0.f, d1 = 0.f, d2 = 0.f, d3 = 0.f;
            asm volatile(
                "mma.sync.aligned.m16n8k16.row.col.f32.bf16.bf16.f32 "
                "{%0,%1,%2,%3}, {%4,%5,%6,%7}, {%8,%9}, {%0,%1,%2,%3};"
                : "+f"(d0), "+f"(d1), "+f"(d2), "+f"(d3)
                : "r"(a0[0]), "r"(a0[1]), "r"(a0[2]), "r"(a0[3]),
                  "r"(bf0[nt][0]), "r"(bf1[nt][0]));
            asm volatile(
                "mma.sync.aligned.m16n8k16.row.col.f32.bf16.bf16.f32 "
                "{%0,%1,%2,%3}, {%4,%5,%6,%7}, {%8,%9}, {%0,%1,%2,%3};"
                : "+f"(d0), "+f"(d1), "+f"(d2), "+f"(d3)
                : "r"(a1[0]), "r"(a1[1]), "r"(a1[2]), "r"(a1[3]),
                  "r"(bf0[nt][1]), "r"(bf1[nt][1]));

            const float2 wv = *(const float2*)&sWeff[8 * nt + 2 * c];
            float s0, s1v, s2v, s3v;
            asm("sin.approx.f32 %0, %1;" : "=f"(s0)  : "f"(d0));
            asm("sin.approx.f32 %0, %1;" : "=f"(s1v) : "f"(d1));
            asm("sin.approx.f32 %0, %1;" : "=f"(s2v) : "f"(d2));
            asm("sin.approx.f32 %0, %1;" : "=f"(s3v) : "f"(d3));
            accA = fmaf(s0,  wv.x, accA);
            accA = fmaf(s1v, wv.y, accA);
            accB = fmaf(s2v, wv.x, accB);
            accB = fmaf(s3v, wv.y, accB);
        }

        // reduce over the 4 lanes (c=0..3) sharing the same sample rows
        accA += __shfl_xor_sync(0xffffffffu, accA, 1);
        accA += __shfl_xor_sync(0xffffffffu, accA, 2);
        accB += __shfl_xor_sync(0xffffffffu, accB, 1);
        accB += __shfl_xor_sync(0xffffffffu, accB, 2);

        const float envG  = __shfl_sync(0xffffffffu, env, g);
        const float envG8 = __shfl_sync(0xffffffffu, env, g + 8);

        if (c == 0) outp[g]     = envG  * (accA + cv);
        if (c == 1) outp[g + 8] = envG8 * (accB + cv);
        outp += ostep;
    }

    // ---- reset flags for the next launch (deterministic across replays) ----
    __syncthreads();
    if (t == 0) {
        __threadfence();
        const int old = atomicAdd(&g_exit, 1);
        if (old == (int)gridDim.x - 1) {
            g_ready = 0;
            g_exit = 0;
            __threadfence();
        }
    }
}

// ---------------------------------------------------------------------------
extern "C" void kernel_launch(void* const* d_in, const int* in_sizes, int n_in,
                              void* d_out, int out_size) {
    const float* x     = (const float*)d_in[0];
    const float* Wt    = (const float*)d_in[1];
    const float* bt    = (const float*)d_in[2];
    const float* Wleaf = (const float*)d_in[3];
    const float* bleaf = (const float*)d_in[4];
    const float* W3    = (const float*)d_in[5];
    const float* b3    = (const float*)d_in[6];
    const float* W2    = (const float*)d_in[7];
    const float* b2    = (const float*)d_in[8];
    const float* W1    = (const float*)d_in[9];
    const float* b1    = (const float*)d_in[10];
    const float* Wr    = (const float*)d_in[11];
    const float* br    = (const float*)d_in[12];
    float* out = (float*)d_out;

    const int N = in_sizes[0] / 10;
    const int n_chunks = (N + 15) / 16;

    // single fully-resident wave: 148 SMs x 3 blocks x 8 warps = 3552 warps
    const int cap_warps = 148 * 3 * 8;
    int iters = (n_chunks + cap_warps - 1) / cap_warps;
    int grid = (n_chunks + 8 * iters - 1) / (8 * iters);
    if (grid < 16) grid = 16;
    if (grid > 148 * 3) grid = 148 * 3;

    fused_kernel<<<grid, 256>>>(x, Wt, bt, Wleaf, bleaf, W3, b3, W2, b2,
                                W1, b1, Wr, br, out, N, n_chunks);
}

// round 9
// speedup vs baseline: 1.0765x; 1.0765x over previous
#include <cuda_runtime.h>
#include <cuda_bf16.h>
#include <cstdint>

// ===========================================================================
// TrainableTree: out[n] = a(x_n) * ( sin(Wt x_n + bt) . w_eff + c )
// Tree after sin() is linear with OUT=1 -> collapses to (w_eff[64], c).
// compose_kernel: 16 blocks, weights register-resident (one latency round).
// tree_main_kernel: HMMA (bf16 hi/lo split, fp32 accum) -> MUFU sin -> dot.
//   B-fragments live in SMEM (LDS.128 per n-tile) to cut regs -> 8 blocks/SM.
// ===========================================================================

__device__ float g_part[16][64];   // per-leaf partials of w_eff
__device__ float c_part[16];       // per-leaf partials of c

// ---------------- helpers ----------------
__device__ __forceinline__ uint32_t bfpk(float lo, float hi) {
    uint32_t d;
    asm("cvt.rn.bf16x2.f32 %0, %1, %2;" : "=r"(d) : "f"(hi), "f"(lo));
    return d;   // lower 16 = bf16(lo), upper 16 = bf16(hi)
}
__device__ __forceinline__ float bflo(uint32_t p) { return __uint_as_float(p << 16); }
__device__ __forceinline__ float bfhi(uint32_t p) { return __uint_as_float(p & 0xffff0000u); }

// ---------------------------------------------------------------------------
// Compose: 16 blocks x 256 thr; block k needs W1[k>>3], W2[k>>2], W3[k>>1],
// Wleaf[k]; all weight slices register-resident (single DRAM latency round).
// ---------------------------------------------------------------------------
__global__ void __launch_bounds__(256)
compose_kernel(const float* __restrict__ Wleaf, const float* __restrict__ bleaf,
               const float* __restrict__ W3, const float* __restrict__ b3,
               const float* __restrict__ W2, const float* __restrict__ b2,
               const float* __restrict__ W1, const float* __restrict__ b1,
               const float* __restrict__ Wr, const float* __restrict__ br) {
    __shared__ float sGr[64], sG1[64], sG2[64], sG3[64];
    __shared__ float red[4][64];
    __shared__ float cp[64];

    const int t = threadIdx.x;
    const int k = blockIdx.x;
    const int o = t & 63, q = t >> 6;   // q in 0..3
    const int p0 = q * 16;

    const float* W1n = W1 + (k >> 3) * 4096;
    const float* W2n = W2 + (k >> 2) * 4096;
    const float* W3n = W3 + (k >> 1) * 4096;
    const float* WLn = Wleaf + k * 4096;
    float w1r[16], w2r[16], w3r[16], wlr[16];
    #pragma unroll
    for (int i = 0; i < 16; i++) w1r[i] = W1n[(p0 + i) * 64 + o];
    #pragma unroll
    for (int i = 0; i < 16; i++) w2r[i] = W2n[(p0 + i) * 64 + o];
    #pragma unroll
    for (int i = 0; i < 16; i++) w3r[i] = W3n[(p0 + i) * 64 + o];
    #pragma unroll
    for (int i = 0; i < 16; i++) wlr[i] = WLn[(p0 + i) * 64 + o];

    const float blf = bleaf[k * 64 + o];
    const float b3v = ((k & 1) == 0) ? b3[(k >> 1) * 64 + o] : 0.f;
    const float b2v = ((k & 3) == 0) ? b2[(k >> 2) * 64 + o] : 0.f;
    const float b1v = (k == 0) ? (b1[o] + b1[64 + o]) : 0.f;

    if (t < 64) sGr[t] = Wr[t];
    __syncthreads();

    {
        float s = 0.f;
        #pragma unroll
        for (int i = 0; i < 16; i++) s = fmaf(w1r[i], sGr[p0 + i], s);
        red[q][o] = s;
    }
    __syncthreads();
    if (t < 64) sG1[t] = red[0][t] + red[1][t] + red[2][t] + red[3][t];
    __syncthreads();
    {
        float s = 0.f;
        #pragma unroll
        for (int i = 0; i < 16; i++) s = fmaf(w2r[i], sG1[p0 + i], s);
        red[q][o] = s;
    }
    __syncthreads();
    if (t < 64) sG2[t] = red[0][t] + red[1][t] + red[2][t] + red[3][t];
    __syncthreads();
    {
        float s = 0.f;
        #pragma unroll
        for (int i = 0; i < 16; i++) s = fmaf(w3r[i], sG2[p0 + i], s);
        red[q][o] = s;
    }
    __syncthreads();
    if (t < 64) sG3[t] = red[0][t] + red[1][t] + red[2][t] + red[3][t];
    __syncthreads();
    {
        float s = 0.f;
        #pragma unroll
        for (int i = 0; i < 16; i++) s = fmaf(wlr[i], sG3[p0 + i], s);
        red[q][o] = s;
    }
    __syncthreads();
    if (t < 64) g_part[k][t] = red[0][t] + red[1][t] + red[2][t] + red[3][t];

    if (t < 64) {
        float s = sG3[o] * blf;
        s = fmaf(sG2[o], b3v, s);
        s = fmaf(sG1[o], b2v, s);
        s = fmaf(sGr[o], b1v, s);
        cp[o] = s;
    }
    __syncthreads();
    if (t == 0) {
        float s = (k == 0) ? br[0] : 0.f;
        #pragma unroll 8
        for (int i = 0; i < 64; i++) s += cp[i];
        c_part[k] = s;
    }
}

// ---------------------------------------------------------------------------
// Main kernel. 16 samples per warp-iteration.
//   A (x) tile: 16 rows x 32 K bf16 in smem (80B rows, conflict-free ldmatrix)
//   K cols: [x_hi(10) | x_lo(10) | x_hi(10) | 1, 1]
//   B cols: [W_hi(10) | W_hi(10) | W_lo(10) | bt_hi, bt_lo]
//   h = x_hi.W_hi + x_lo.W_hi + x_hi.W_lo + bt   (fp32 accum, ~1e-5 rel)
//   Per-lane B fragments precomputed to SMEM; hot loop: LDS.128 per n-tile.
// ---------------------------------------------------------------------------
__global__ void __launch_bounds__(128, 8)
tree_main_kernel(const float* __restrict__ x, const float* __restrict__ Wt,
                 const float* __restrict__ bt, float* __restrict__ out,
                 int N, int n_chunks) {
    __shared__ uint32_t sB[64][18];       // [out][k-pair], 72B rows
    __shared__ uint32_t sA[4][16][20];    // per warp: 16 rows x 80B
    __shared__ uint4 sFrag[8][32];        // [n-tile][lane] = {b00,b10,b01,b11}
    __shared__ float sWeff[64];
    __shared__ float sC[1];

    const int t = threadIdx.x;
    const int wid = t >> 5, lane = t & 31;
    const int c = lane & 3, g = lane >> 2;

    // ---- reduce w_eff / c from compose partials ----
    if (t < 64) {
        float s = 0.f;
        #pragma unroll
        for (int k = 0; k < 16; k++) s += g_part[k][t];
        sWeff[t] = s;
    }
    if (t == 64) {
        float s = 0.f;
        #pragma unroll
        for (int k = 0; k < 16; k++) s += c_part[k];
        sC[0] = s;
    }

    // ---- build B tile (thread t = output t) ----
    if (t < 64) {
        const float2* wr = (const float2*)(Wt + t * 10);
        uint32_t H[5], L[5];
        #pragma unroll
        for (int j = 0; j < 5; j++) {
            const float2 v = wr[j];
            H[j] = bfpk(v.x, v.y);
            L[j] = bfpk(v.x - bflo(H[j]), v.y - bfhi(H[j]));
        }
        const float bv = bt[t];
        const uint32_t bh = bfpk(bv, 0.f);
        const uint32_t bp = bfpk(bv, bv - bflo(bh));   // {bt_hi, bt_lo}
        #pragma unroll
        for (int j = 0; j < 5; j++) {
            sB[t][j]      = H[j];   // k 0-9  : W_hi
            sB[t][5 + j]  = H[j];   // k 10-19: W_hi
            sB[t][10 + j] = L[j];   // k 20-29: W_lo
        }
        sB[t][15] = bp;             // k 30,31: bt_hi, bt_lo
        sB[t][16] = 0u; sB[t][17] = 0u;
    }
    __syncthreads();

    // ---- precompute per-lane B fragments into smem (warp 0) ----
    if (wid == 0) {
        #pragma unroll
        for (int nt = 0; nt < 8; nt++) {
            const int row = 8 * nt + g;
            sFrag[nt][lane] = make_uint4(sB[row][c],     sB[row][4 + c],
                                         sB[row][8 + c], sB[row][12 + c]);
        }
    }
    __syncthreads();
    const float cv = sC[0];

    const int s16 = lane & 15;
    const int lm_sub = lane >> 3, lm_r = lane & 7;
    const int lm_row = lm_r + 8 * (lm_sub & 1);
    const uint32_t lm_base =
        (uint32_t)__cvta_generic_to_shared(&sA[wid][lm_row][0]) + (lm_sub >> 1) * 16;

    const int wglobal = blockIdx.x * 4 + wid;
    const int wstride = gridDim.x * 4;

    for (int ch = wglobal; ch < n_chunks; ch += wstride) {
        const int row = ch * 16 + s16;
        float xv[10];
        {
            const float2* p = (const float2*)(x + (size_t)row * 10);
            #pragma unroll
            for (int i = 0; i < 5; i++) { float2 v = p[i]; xv[2*i] = v.x; xv[2*i+1] = v.y; }
        }

        // envelope
        float env = fmaf(xv[0], xv[0], -1.f);
        #pragma unroll
        for (int d = 1; d < 10; d++) env *= fmaf(xv[d], xv[d], -1.f);
        env = env * rsqrtf(fmaf(env, env, 1000.f));

        // stage A row (2 lanes per sample; lane<16: k-pairs 0-7, else 8-15)
        uint32_t H[5];
        #pragma unroll
        for (int j = 0; j < 5; j++) H[j] = bfpk(xv[2 * j], xv[2 * j + 1]);
        uint32_t* arow = sA[wid][s16];
        if (lane < 16) {
            const uint32_t L0 = bfpk(xv[0] - bflo(H[0]), xv[1] - bfhi(H[0]));
            const uint32_t L1 = bfpk(xv[2] - bflo(H[1]), xv[3] - bfhi(H[1]));
            const uint32_t L2 = bfpk(xv[4] - bflo(H[2]), xv[5] - bfhi(H[2]));
            *(uint4*)&arow[0] = make_uint4(H[0], H[1], H[2], H[3]);
            *(uint4*)&arow[4] = make_uint4(H[4], L0, L1, L2);
        } else {
            const uint32_t L3 = bfpk(xv[6] - bflo(H[3]), xv[7] - bfhi(H[3]));
            const uint32_t L4 = bfpk(xv[8] - bflo(H[4]), xv[9] - bfhi(H[4]));
            *(uint4*)&arow[8]  = make_uint4(L3, L4, H[0], H[1]);
            *(uint4*)&arow[12] = make_uint4(H[2], H[3], H[4], 0x3f803f80u); // ones
        }
        __syncwarp();

        uint32_t a0[4], a1[4];
        asm volatile("ldmatrix.sync.aligned.m8n8.x4.shared.b16 {%0,%1,%2,%3}, [%4];"
                     : "=r"(a0[0]), "=r"(a0[1]), "=r"(a0[2]), "=r"(a0[3])
                     : "r"(lm_base));
        asm volatile("ldmatrix.sync.aligned.m8n8.x4.shared.b16 {%0,%1,%2,%3}, [%4];"
                     : "=r"(a1[0]), "=r"(a1[1]), "=r"(a1[2]), "=r"(a1[3])
                     : "r"(lm_base + 32));

        float accA = 0.f, accB = 0.f;
        #pragma unroll
        for (int nt = 0; nt < 8; nt++) {
            const uint4 bf = sFrag[nt][lane];
            float d0 = 0.f, d1 = 0.f, d2 = 0.f, d3 = 0.f;
            asm volatile(
                "mma.sync.aligned.m16n8k16.row.col.f32.bf16.bf16.f32 "
                "{%0,%1,%2,%3}, {%4,%5,%6,%7}, {%8,%9}, {%0,%1,%2,%3};"
                : "+f"(d0), "+f"(d1), "+f"(d2), "+f"(d3)
                : "r"(a0[0]), "r"(a0[1]), "r"(a0[2]), "r"(a0[3]),
                  "r"(bf.x), "r"(bf.y));
            asm volatile(
                "mma.sync.aligned.m16n8k16.row.col.f32.bf16.bf16.f32 "
                "{%0,%1,%2,%3}, {%4,%5,%6,%7}, {%8,%9}, {%0,%1,%2,%3};"
                : "+f"(d0), "+f"(d1), "+f"(d2), "+f"(d3)
                : "r"(a1[0]), "r"(a1[1]), "r"(a1[2]), "r"(a1[3]),
                  "r"(bf.z), "r"(bf.w));

            const float2 wv = *(const float2*)&sWeff[8 * nt + 2 * c];
            float s0, s1v, s2v, s3v;
            asm("sin.approx.f32 %0, %1;" : "=f"(s0)  : "f"(d0));
            asm("sin.approx.f32 %0, %1;" : "=f"(s1v) : "f"(d1));
            asm("sin.approx.f32 %0, %1;" : "=f"(s2v) : "f"(d2));
            asm("sin.approx.f32 %0, %1;" : "=f"(s3v) : "f"(d3));
            accA = fmaf(s0,  wv.x, accA);
            accA = fmaf(s1v, wv.y, accA);
            accB = fmaf(s2v, wv.x, accB);
            accB = fmaf(s3v, wv.y, accB);
        }

        // reduce over the 4 lanes (c=0..3) sharing the same sample rows
        accA += __shfl_xor_sync(0xffffffffu, accA, 1);
        accA += __shfl_xor_sync(0xffffffffu, accA, 2);
        accB += __shfl_xor_sync(0xffffffffu, accB, 1);
        accB += __shfl_xor_sync(0xffffffffu, accB, 2);

        const float envG  = __shfl_sync(0xffffffffu, env, g);
        const float envG8 = __shfl_sync(0xffffffffu, env, g + 8);

        const int base = ch * 16;
        if (c == 0 && base + g < N)     out[base + g]     = envG  * (accA + cv);
        if (c == 1 && base + g + 8 < N) out[base + g + 8] = envG8 * (accB + cv);
    }
}

// ---------------------------------------------------------------------------
extern "C" void kernel_launch(void* const* d_in, const int* in_sizes, int n_in,
                              void* d_out, int out_size) {
    const float* x     = (const float*)d_in[0];
    const float* Wt    = (const float*)d_in[1];
    const float* bt    = (const float*)d_in[2];
    const float* Wleaf = (const float*)d_in[3];
    const float* bleaf = (const float*)d_in[4];
    const float* W3    = (const float*)d_in[5];
    const float* b3    = (const float*)d_in[6];
    const float* W2    = (const float*)d_in[7];
    const float* b2    = (const float*)d_in[8];
    const float* W1    = (const float*)d_in[9];
    const float* b1    = (const float*)d_in[10];
    const float* Wr    = (const float*)d_in[11];
    const float* br    = (const float*)d_in[12];
    float* out = (float*)d_out;

    const int N = in_sizes[0] / 10;
    const int n_chunks = (N + 15) / 16;

    compose_kernel<<<16, 256>>>(Wleaf, bleaf, W3, b3, W2, b2, W1, b1, Wr, br);

    // exact fit: 1024 blocks x 4 warps x 4 chunks = 16384 chunks, one wave
    int grid = (n_chunks + 15) / 16;
    if (grid < 1) grid = 1;
    tree_main_kernel<<<grid, 128>>>(x, Wt, bt, out, N, n_chunks);
}

// round 10
// speedup vs baseline: 1.0866x; 1.0094x over previous
#include <cuda_runtime.h>
#include <cuda_bf16.h>
#include <cstdint>

// ===========================================================================
// TrainableTree: out[n] = a(x_n) * ( sin(Wt x_n + bt) . w_eff + c )
// Tree after sin() is linear with OUT=1 -> collapses to (w_eff[64], c).
// compose_kernel: 16 blocks, weights register-resident (one latency round).
// tree_main_kernel: 2 chunks (32 samples) per warp-iteration for ILP.
//   HMMA (bf16 hi/lo split, fp32 accum) -> MUFU sin -> dot -> envelope.
// ===========================================================================

__device__ float g_part[16][64];   // per-leaf partials of w_eff
__device__ float c_part[16];       // per-leaf partials of c

// ---------------- helpers ----------------
__device__ __forceinline__ uint32_t bfpk(float lo, float hi) {
    uint32_t d;
    asm("cvt.rn.bf16x2.f32 %0, %1, %2;" : "=r"(d) : "f"(hi), "f"(lo));
    return d;   // lower 16 = bf16(lo), upper 16 = bf16(hi)
}
__device__ __forceinline__ float bflo(uint32_t p) { return __uint_as_float(p << 16); }
__device__ __forceinline__ float bfhi(uint32_t p) { return __uint_as_float(p & 0xffff0000u); }

#define MMA16816(d0,d1,d2,d3,a,b0,b1) \
    asm volatile( \
        "mma.sync.aligned.m16n8k16.row.col.f32.bf16.bf16.f32 " \
        "{%0,%1,%2,%3}, {%4,%5,%6,%7}, {%8,%9}, {%0,%1,%2,%3};" \
        : "+f"(d0), "+f"(d1), "+f"(d2), "+f"(d3) \
        : "r"((a)[0]), "r"((a)[1]), "r"((a)[2]), "r"((a)[3]), \
          "r"(b0), "r"(b1))

// ---------------------------------------------------------------------------
// Compose: 16 blocks x 256 thr; block k needs W1[k>>3], W2[k>>2], W3[k>>1],
// Wleaf[k]; all weight slices register-resident (single DRAM latency round).
// ---------------------------------------------------------------------------
__global__ void __launch_bounds__(256)
compose_kernel(const float* __restrict__ Wleaf, const float* __restrict__ bleaf,
               const float* __restrict__ W3, const float* __restrict__ b3,
               const float* __restrict__ W2, const float* __restrict__ b2,
               const float* __restrict__ W1, const float* __restrict__ b1,
               const float* __restrict__ Wr, const float* __restrict__ br) {
    __shared__ float sGr[64], sG1[64], sG2[64], sG3[64];
    __shared__ float red[4][64];
    __shared__ float cp[64];

    const int t = threadIdx.x;
    const int k = blockIdx.x;
    const int o = t & 63, q = t >> 6;   // q in 0..3
    const int p0 = q * 16;

    const float* W1n = W1 + (k >> 3) * 4096;
    const float* W2n = W2 + (k >> 2) * 4096;
    const float* W3n = W3 + (k >> 1) * 4096;
    const float* WLn = Wleaf + k * 4096;
    float w1r[16], w2r[16], w3r[16], wlr[16];
    #pragma unroll
    for (int i = 0; i < 16; i++) w1r[i] = W1n[(p0 + i) * 64 + o];
    #pragma unroll
    for (int i = 0; i < 16; i++) w2r[i] = W2n[(p0 + i) * 64 + o];
    #pragma unroll
    for (int i = 0; i < 16; i++) w3r[i] = W3n[(p0 + i) * 64 + o];
    #pragma unroll
    for (int i = 0; i < 16; i++) wlr[i] = WLn[(p0 + i) * 64 + o];

    const float blf = bleaf[k * 64 + o];
    const float b3v = ((k & 1) == 0) ? b3[(k >> 1) * 64 + o] : 0.f;
    const float b2v = ((k & 3) == 0) ? b2[(k >> 2) * 64 + o] : 0.f;
    const float b1v = (k == 0) ? (b1[o] + b1[64 + o]) : 0.f;

    if (t < 64) sGr[t] = Wr[t];
    __syncthreads();

    {
        float s = 0.f;
        #pragma unroll
        for (int i = 0; i < 16; i++) s = fmaf(w1r[i], sGr[p0 + i], s);
        red[q][o] = s;
    }
    __syncthreads();
    if (t < 64) sG1[t] = red[0][t] + red[1][t] + red[2][t] + red[3][t];
    __syncthreads();
    {
        float s = 0.f;
        #pragma unroll
        for (int i = 0; i < 16; i++) s = fmaf(w2r[i], sG1[p0 + i], s);
        red[q][o] = s;
    }
    __syncthreads();
    if (t < 64) sG2[t] = red[0][t] + red[1][t] + red[2][t] + red[3][t];
    __syncthreads();
    {
        float s = 0.f;
        #pragma unroll
        for (int i = 0; i < 16; i++) s = fmaf(w3r[i], sG2[p0 + i], s);
        red[q][o] = s;
    }
    __syncthreads();
    if (t < 64) sG3[t] = red[0][t] + red[1][t] + red[2][t] + red[3][t];
    __syncthreads();
    {
        float s = 0.f;
        #pragma unroll
        for (int i = 0; i < 16; i++) s = fmaf(wlr[i], sG3[p0 + i], s);
        red[q][o] = s;
    }
    __syncthreads();
    if (t < 64) g_part[k][t] = red[0][t] + red[1][t] + red[2][t] + red[3][t];

    if (t < 64) {
        float s = sG3[o] * blf;
        s = fmaf(sG2[o], b3v, s);
        s = fmaf(sG1[o], b2v, s);
        s = fmaf(sGr[o], b1v, s);
        cp[o] = s;
    }
    __syncthreads();
    if (t == 0) {
        float s = (k == 0) ? br[0] : 0.f;
        #pragma unroll 8
        for (int i = 0; i < 64; i++) s += cp[i];
        c_part[k] = s;
    }
}

// ---------------------------------------------------------------------------
// Main kernel: per warp-iteration 2 chunks = 32 samples.
//   A tile: 32 rows x 32 K bf16 in smem (80B rows, conflict-free ldmatrix)
//   K cols: [x_hi(10) | x_lo(10) | x_hi(10) | 1, 1]
//   B cols: [W_hi(10) | W_hi(10) | W_lo(10) | bt_hi, bt_lo]
//   h = x_hi.W_hi + x_lo.W_hi + x_hi.W_lo + bt   (fp32 accum, ~1e-5 rel)
//   Per-lane B fragments in SMEM; each frag LDS feeds 4 MMAs.
// ---------------------------------------------------------------------------
__global__ void __launch_bounds__(128, 7)
tree_main_kernel(const float* __restrict__ x, const float* __restrict__ Wt,
                 const float* __restrict__ bt, float* __restrict__ out,
                 int N, int n_pairs) {
    __shared__ uint32_t sB[64][18];       // [out][k-pair], 72B rows
    __shared__ uint32_t sA[4][32][20];    // per warp: 32 rows x 80B
    __shared__ uint4 sFrag[8][32];        // [n-tile][lane] = {b00,b10,b01,b11}
    __shared__ float sWeff[64];
    __shared__ float sC[1];

    const int t = threadIdx.x;
    const int wid = t >> 5, lane = t & 31;
    const int c = lane & 3, g = lane >> 2;

    // ---- reduce w_eff / c from compose partials ----
    if (t < 64) {
        float s = 0.f;
        #pragma unroll
        for (int k = 0; k < 16; k++) s += g_part[k][t];
        sWeff[t] = s;
    }
    if (t == 64) {
        float s = 0.f;
        #pragma unroll
        for (int k = 0; k < 16; k++) s += c_part[k];
        sC[0] = s;
    }

    // ---- build B tile (thread t = output t) ----
    if (t < 64) {
        const float2* wr = (const float2*)(Wt + t * 10);
        uint32_t H[5], L[5];
        #pragma unroll
        for (int j = 0; j < 5; j++) {
            const float2 v = wr[j];
            H[j] = bfpk(v.x, v.y);
            L[j] = bfpk(v.x - bflo(H[j]), v.y - bfhi(H[j]));
        }
        const float bv = bt[t];
        const uint32_t bh = bfpk(bv, 0.f);
        const uint32_t bp = bfpk(bv, bv - bflo(bh));   // {bt_hi, bt_lo}
        #pragma unroll
        for (int j = 0; j < 5; j++) {
            sB[t][j]      = H[j];   // k 0-9  : W_hi
            sB[t][5 + j]  = H[j];   // k 10-19: W_hi
            sB[t][10 + j] = L[j];   // k 20-29: W_lo
        }
        sB[t][15] = bp;             // k 30,31: bt_hi, bt_lo
        sB[t][16] = 0u; sB[t][17] = 0u;
    }
    __syncthreads();

    // ---- precompute per-lane B fragments into smem (warp 0) ----
    if (wid == 0) {
        #pragma unroll
        for (int nt = 0; nt < 8; nt++) {
            const int row = 8 * nt + g;
            sFrag[nt][lane] = make_uint4(sB[row][c],     sB[row][4 + c],
                                         sB[row][8 + c], sB[row][12 + c]);
        }
    }
    __syncthreads();
    const float cv = sC[0];

    const int s16 = lane & 15;
    const int lm_sub = lane >> 3, lm_r = lane & 7;
    const int lm_row = lm_r + 8 * (lm_sub & 1);
    const uint32_t lm_base =
        (uint32_t)__cvta_generic_to_shared(&sA[wid][lm_row][0]) + (lm_sub >> 1) * 16;
    const uint32_t lm_base2 = lm_base + 16 * 80;   // rows 16-31 (chunk 1)

    const int wglobal = blockIdx.x * 4 + wid;
    const int wstride = gridDim.x * 4;

    for (int pr = wglobal; pr < n_pairs; pr += wstride) {
        const int base = pr * 32;                // first sample of chunk pair
        const int r0 = base + s16;
        const int r1 = r0 + 16;
        const int r0c = (r0 < N) ? r0 : (N - 1);
        const int r1c = (r1 < N) ? r1 : (N - 1);

        float xv0[10], xv1[10];
        {
            const float2* p = (const float2*)(x + (size_t)r0c * 10);
            #pragma unroll
            for (int i = 0; i < 5; i++) { float2 v = p[i]; xv0[2*i] = v.x; xv0[2*i+1] = v.y; }
            const float2* q2 = (const float2*)(x + (size_t)r1c * 10);
            #pragma unroll
            for (int i = 0; i < 5; i++) { float2 v = q2[i]; xv1[2*i] = v.x; xv1[2*i+1] = v.y; }
        }

        // envelopes
        float env0 = fmaf(xv0[0], xv0[0], -1.f);
        float env1 = fmaf(xv1[0], xv1[0], -1.f);
        #pragma unroll
        for (int d = 1; d < 10; d++) {
            env0 *= fmaf(xv0[d], xv0[d], -1.f);
            env1 *= fmaf(xv1[d], xv1[d], -1.f);
        }
        env0 = env0 * rsqrtf(fmaf(env0, env0, 1000.f));
        env1 = env1 * rsqrtf(fmaf(env1, env1, 1000.f));

        // stage both A rows (2 lanes per sample row)
        {
            uint32_t H[5];
            #pragma unroll
            for (int j = 0; j < 5; j++) H[j] = bfpk(xv0[2 * j], xv0[2 * j + 1]);
            uint32_t* arow = sA[wid][s16];
            if (lane < 16) {
                const uint32_t L0 = bfpk(xv0[0] - bflo(H[0]), xv0[1] - bfhi(H[0]));
                const uint32_t L1 = bfpk(xv0[2] - bflo(H[1]), xv0[3] - bfhi(H[1]));
                const uint32_t L2 = bfpk(xv0[4] - bflo(H[2]), xv0[5] - bfhi(H[2]));
                *(uint4*)&arow[0] = make_uint4(H[0], H[1], H[2], H[3]);
                *(uint4*)&arow[4] = make_uint4(H[4], L0, L1, L2);
            } else {
                const uint32_t L3 = bfpk(xv0[6] - bflo(H[3]), xv0[7] - bfhi(H[3]));
                const uint32_t L4 = bfpk(xv0[8] - bflo(H[4]), xv0[9] - bfhi(H[4]));
                *(uint4*)&arow[8]  = make_uint4(L3, L4, H[0], H[1]);
                *(uint4*)&arow[12] = make_uint4(H[2], H[3], H[4], 0x3f803f80u);
            }
        }
        {
            uint32_t H[5];
            #pragma unroll
            for (int j = 0; j < 5; j++) H[j] = bfpk(xv1[2 * j], xv1[2 * j + 1]);
            uint32_t* arow = sA[wid][s16 + 16];
            if (lane < 16) {
                const uint32_t L0 = bfpk(xv1[0] - bflo(H[0]), xv1[1] - bfhi(H[0]));
                const uint32_t L1 = bfpk(xv1[2] - bflo(H[1]), xv1[3] - bfhi(H[1]));
                const uint32_t L2 = bfpk(xv1[4] - bflo(H[2]), xv1[5] - bfhi(H[2]));
                *(uint4*)&arow[0] = make_uint4(H[0], H[1], H[2], H[3]);
                *(uint4*)&arow[4] = make_uint4(H[4], L0, L1, L2);
            } else {
                const uint32_t L3 = bfpk(xv1[6] - bflo(H[3]), xv1[7] - bfhi(H[3]));
                const uint32_t L4 = bfpk(xv1[8] - bflo(H[4]), xv1[9] - bfhi(H[4]));
                *(uint4*)&arow[8]  = make_uint4(L3, L4, H[0], H[1]);
                *(uint4*)&arow[12] = make_uint4(H[2], H[3], H[4], 0x3f803f80u);
            }
        }
        __syncwarp();

        uint32_t a0[4], a1[4], a2[4], a3[4];
        asm volatile("ldmatrix.sync.aligned.m8n8.x4.shared.b16 {%0,%1,%2,%3}, [%4];"
                     : "=r"(a0[0]), "=r"(a0[1]), "=r"(a0[2]), "=r"(a0[3])
                     : "r"(lm_base));
        asm volatile("ldmatrix.sync.aligned.m8n8.x4.shared.b16 {%0,%1,%2,%3}, [%4];"
                     : "=r"(a1[0]), "=r"(a1[1]), "=r"(a1[2]), "=r"(a1[3])
                     : "r"(lm_base + 32));
        asm volatile("ldmatrix.sync.aligned.m8n8.x4.shared.b16 {%0,%1,%2,%3}, [%4];"
                     : "=r"(a2[0]), "=r"(a2[1]), "=r"(a2[2]), "=r"(a2[3])
                     : "r"(lm_base2));
        asm volatile("ldmatrix.sync.aligned.m8n8.x4.shared.b16 {%0,%1,%2,%3}, [%4];"
                     : "=r"(a3[0]), "=r"(a3[1]), "=r"(a3[2]), "=r"(a3[3])
                     : "r"(lm_base2 + 32));

        float accA0 = 0.f, accB0 = 0.f, accA1 = 0.f, accB1 = 0.f;
        #pragma unroll
        for (int nt = 0; nt < 8; nt++) {
            const uint4 bf = sFrag[nt][lane];
            float d0 = 0.f, d1 = 0.f, d2 = 0.f, d3 = 0.f;
            float e0 = 0.f, e1 = 0.f, e2 = 0.f, e3 = 0.f;
            MMA16816(d0, d1, d2, d3, a0, bf.x, bf.y);
            MMA16816(e0, e1, e2, e3, a2, bf.x, bf.y);
            MMA16816(d0, d1, d2, d3, a1, bf.z, bf.w);
            MMA16816(e0, e1, e2, e3, a3, bf.z, bf.w);

            const float2 wv = *(const float2*)&sWeff[8 * nt + 2 * c];
            float s0, s1, s2, s3, u0, u1, u2, u3;
            asm("sin.approx.f32 %0, %1;" : "=f"(s0) : "f"(d0));
            asm("sin.approx.f32 %0, %1;" : "=f"(s1) : "f"(d1));
            asm("sin.approx.f32 %0, %1;" : "=f"(s2) : "f"(d2));
            asm("sin.approx.f32 %0, %1;" : "=f"(s3) : "f"(d3));
            asm("sin.approx.f32 %0, %1;" : "=f"(u0) : "f"(e0));
            asm("sin.approx.f32 %0, %1;" : "=f"(u1) : "f"(e1));
            asm("sin.approx.f32 %0, %1;" : "=f"(u2) : "f"(e2));
            asm("sin.approx.f32 %0, %1;" : "=f"(u3) : "f"(e3));
            accA0 = fmaf(s0, wv.x, accA0);
            accA0 = fmaf(s1, wv.y, accA0);
            accB0 = fmaf(s2, wv.x, accB0);
            accB0 = fmaf(s3, wv.y, accB0);
            accA1 = fmaf(u0, wv.x, accA1);
            accA1 = fmaf(u1, wv.y, accA1);
            accB1 = fmaf(u2, wv.x, accB1);
            accB1 = fmaf(u3, wv.y, accB1);
        }

        // reduce over the 4 lanes (c=0..3) sharing the same sample rows
        accA0 += __shfl_xor_sync(0xffffffffu, accA0, 1);
        accB0 += __shfl_xor_sync(0xffffffffu, accB0, 1);
        accA1 += __shfl_xor_sync(0xffffffffu, accA1, 1);
        accB1 += __shfl_xor_sync(0xffffffffu, accB1, 1);
        accA0 += __shfl_xor_sync(0xffffffffu, accA0, 2);
        accB0 += __shfl_xor_sync(0xffffffffu, accB0, 2);
        accA1 += __shfl_xor_sync(0xffffffffu, accA1, 2);
        accB1 += __shfl_xor_sync(0xffffffffu, accB1, 2);

        const float e0G  = __shfl_sync(0xffffffffu, env0, g);
        const float e0G8 = __shfl_sync(0xffffffffu, env0, g + 8);
        const float e1G  = __shfl_sync(0xffffffffu, env1, g);
        const float e1G8 = __shfl_sync(0xffffffffu, env1, g + 8);

        if (c == 0) {
            if (base + g < N)      out[base + g]      = e0G  * (accA0 + cv);
            if (base + 16 + g < N) out[base + 16 + g] = e1G  * (accA1 + cv);
        }
        if (c == 1) {
            if (base + 8 + g < N)  out[base + 8 + g]  = e0G8 * (accB0 + cv);
            if (base + 24 + g < N) out[base + 24 + g] = e1G8 * (accB1 + cv);
        }
    }
}

// ---------------------------------------------------------------------------
extern "C" void kernel_launch(void* const* d_in, const int* in_sizes, int n_in,
                              void* d_out, int out_size) {
    const float* x     = (const float*)d_in[0];
    const float* Wt    = (const float*)d_in[1];
    const float* bt    = (const float*)d_in[2];
    const float* Wleaf = (const float*)d_in[3];
    const float* bleaf = (const float*)d_in[4];
    const float* W3    = (const float*)d_in[5];
    const float* b3    = (const float*)d_in[6];
    const float* W2    = (const float*)d_in[7];
    const float* b2    = (const float*)d_in[8];
    const float* W1    = (const float*)d_in[9];
    const float* b1    = (const float*)d_in[10];
    const float* Wr    = (const float*)d_in[11];
    const float* br    = (const float*)d_in[12];
    float* out = (float*)d_out;

    const int N = in_sizes[0] / 10;
    const int n_pairs = (N + 31) / 32;      // 32 samples per warp-iteration

    compose_kernel<<<16, 256>>>(Wleaf, bleaf, W3, b3, W2, b2, W1, b1, Wr, br);

    // single wave at 7 blocks/SM: 148*7 = 1036 blocks max
    const int cap_warps = 148 * 7 * 4;
    int iters = (n_pairs + cap_warps - 1) / cap_warps;
    int grid = (n_pairs + 4 * iters - 1) / (4 * iters);
    if (grid < 1) grid = 1;
    tree_main_kernel<<<grid, 128>>>(x, Wt, bt, out, N, n_pairs);
}

// round 11
// speedup vs baseline: 1.1248x; 1.0351x over previous
#include <cuda_runtime.h>
#include <cuda_bf16.h>
#include <cstdint>

// ===========================================================================
// TrainableTree: out[n] = a(x_n) * ( sin(Wt x_n + bt) . w_eff + c )
// Tree after sin() is linear with OUT=1 -> collapses to (w_eff[64], c).
// compose_kernel: 16 blocks, double-buffered weight prefetch (32 regs live).
// tree_main_kernel: HMMA (bf16 hi/lo split, fp32 accum) -> MUFU sin -> dot.
//   Uniform (branchless) A staging; B-fragments in SMEM; 8 blocks/SM.
// ===========================================================================

__device__ float g_part[16][64];   // per-leaf partials of w_eff
__device__ float c_part[16];       // per-leaf partials of c

// ---------------- helpers ----------------
__device__ __forceinline__ uint32_t bfpk(float lo, float hi) {
    uint32_t d;
    asm("cvt.rn.bf16x2.f32 %0, %1, %2;" : "=r"(d) : "f"(hi), "f"(lo));
    return d;   // lower 16 = bf16(lo), upper 16 = bf16(hi)
}
__device__ __forceinline__ float bflo(uint32_t p) { return __uint_as_float(p << 16); }
__device__ __forceinline__ float bfhi(uint32_t p) { return __uint_as_float(p & 0xffff0000u); }

// ---------------------------------------------------------------------------
// Compose: 16 blocks x 256 thr. Block k uses W1[k>>3], W2[k>>2], W3[k>>1],
// Wleaf[k]. Double-buffered: stage i+1's 16-elem slice is prefetched while
// stage i computes -> one DRAM latency round total, <=32 weight regs live.
// ---------------------------------------------------------------------------
__global__ void __launch_bounds__(256)
compose_kernel(const float* __restrict__ Wleaf, const float* __restrict__ bleaf,
               const float* __restrict__ W3, const float* __restrict__ b3,
               const float* __restrict__ W2, const float* __restrict__ b2,
               const float* __restrict__ W1, const float* __restrict__ b1,
               const float* __restrict__ Wr, const float* __restrict__ br) {
    __shared__ float sGr[64], sG1[64], sG2[64], sG3[64];
    __shared__ float red[4][64];
    __shared__ float cp[64];

    const int t = threadIdx.x;
    const int k = blockIdx.x;
    const int o = t & 63, q = t >> 6;   // q in 0..3
    const int p0 = q * 16;

    const float* W1n = W1 + (k >> 3) * 4096;
    const float* W2n = W2 + (k >> 2) * 4096;
    const float* W3n = W3 + (k >> 1) * 4096;
    const float* WLn = Wleaf + k * 4096;

    float wA[16], wB[16];
    #pragma unroll
    for (int i = 0; i < 16; i++) wA[i] = W1n[(p0 + i) * 64 + o];   // stage 1
    if (t < 64) sGr[t] = Wr[t];
    __syncthreads();

    // prefetch stage 2 while stage 1 computes
    #pragma unroll
    for (int i = 0; i < 16; i++) wB[i] = W2n[(p0 + i) * 64 + o];
    {
        float s = 0.f;
        #pragma unroll
        for (int i = 0; i < 16; i++) s = fmaf(wA[i], sGr[p0 + i], s);
        red[q][o] = s;
    }
    __syncthreads();
    if (t < 64) sG1[t] = red[0][t] + red[1][t] + red[2][t] + red[3][t];
    __syncthreads();

    // prefetch stage 3
    #pragma unroll
    for (int i = 0; i < 16; i++) wA[i] = W3n[(p0 + i) * 64 + o];
    {
        float s = 0.f;
        #pragma unroll
        for (int i = 0; i < 16; i++) s = fmaf(wB[i], sG1[p0 + i], s);
        red[q][o] = s;
    }
    __syncthreads();
    if (t < 64) sG2[t] = red[0][t] + red[1][t] + red[2][t] + red[3][t];
    __syncthreads();

    // prefetch stage 4 (leaf)
    #pragma unroll
    for (int i = 0; i < 16; i++) wB[i] = WLn[(p0 + i) * 64 + o];
    {
        float s = 0.f;
        #pragma unroll
        for (int i = 0; i < 16; i++) s = fmaf(wA[i], sG2[p0 + i], s);
        red[q][o] = s;
    }
    __syncthreads();
    if (t < 64) sG3[t] = red[0][t] + red[1][t] + red[2][t] + red[3][t];
    __syncthreads();

    {
        float s = 0.f;
        #pragma unroll
        for (int i = 0; i < 16; i++) s = fmaf(wB[i], sG3[p0 + i], s);
        red[q][o] = s;
    }
    __syncthreads();
    if (t < 64) g_part[k][t] = red[0][t] + red[1][t] + red[2][t] + red[3][t];

    // bias partials (each term counted once across blocks)
    if (t < 64) {
        float s = sG3[o] * bleaf[k * 64 + o];
        if ((k & 1) == 0) s = fmaf(sG2[o], b3[(k >> 1) * 64 + o], s);
        if ((k & 3) == 0) s = fmaf(sG1[o], b2[(k >> 2) * 64 + o], s);
        if (k == 0)       s = fmaf(sGr[o], b1[o] + b1[64 + o], s);
        cp[o] = s;
    }
    __syncthreads();
    if (t == 0) {
        float s = (k == 0) ? br[0] : 0.f;
        #pragma unroll 8
        for (int i = 0; i < 64; i++) s += cp[i];
        c_part[k] = s;
    }
}

// ---------------------------------------------------------------------------
// Main kernel. 16 samples per warp-iteration.
//   A (x) tile: 16 rows x 32 K bf16 in smem (80B rows, conflict-free ldmatrix)
//   Row words: [H0..H4 L0 L1 L2 | L3 L4 H0..H4 ONES]   (H=x_hi, L=x_lo pairs)
//   B cols:    [W_hi(10) | W_hi(10) | W_lo(10) | bt_hi, bt_lo]
//   h = x_hi.W_hi + x_lo.W_hi + x_hi.W_lo + bt   (fp32 accum, ~1e-5 rel)
//   Staging is branchless: all lanes compute H/L, SEL by lane>>4, 2x STS.128.
// ---------------------------------------------------------------------------
__global__ void __launch_bounds__(128, 8)
tree_main_kernel(const float* __restrict__ x, const float* __restrict__ Wt,
                 const float* __restrict__ bt, float* __restrict__ out,
                 int N, int n_chunks) {
    __shared__ uint32_t sB[64][18];       // [out][k-pair], 72B rows
    __shared__ uint32_t sA[4][16][20];    // per warp: 16 rows x 80B
    __shared__ uint4 sFrag[8][32];        // [n-tile][lane] = {b00,b10,b01,b11}
    __shared__ float sWeff[64];
    __shared__ float sC[1];

    const int t = threadIdx.x;
    const int wid = t >> 5, lane = t & 31;
    const int c = lane & 3, g = lane >> 2;

    // ---- reduce w_eff / c from compose partials ----
    if (t < 64) {
        float s = 0.f;
        #pragma unroll
        for (int k = 0; k < 16; k++) s += g_part[k][t];
        sWeff[t] = s;
    }
    if (t == 64) {
        float s = 0.f;
        #pragma unroll
        for (int k = 0; k < 16; k++) s += c_part[k];
        sC[0] = s;
    }

    // ---- build B tile (thread t = output t) ----
    if (t < 64) {
        const float2* wr = (const float2*)(Wt + t * 10);
        uint32_t H[5], L[5];
        #pragma unroll
        for (int j = 0; j < 5; j++) {
            const float2 v = wr[j];
            H[j] = bfpk(v.x, v.y);
            L[j] = bfpk(v.x - bflo(H[j]), v.y - bfhi(H[j]));
        }
        const float bv = bt[t];
        const uint32_t bh = bfpk(bv, 0.f);
        const uint32_t bp = bfpk(bv, bv - bflo(bh));   // {bt_hi, bt_lo}
        #pragma unroll
        for (int j = 0; j < 5; j++) {
            sB[t][j]      = H[j];   // k 0-9  : W_hi
            sB[t][5 + j]  = H[j];   // k 10-19: W_hi
            sB[t][10 + j] = L[j];   // k 20-29: W_lo
        }
        sB[t][15] = bp;             // k 30,31: bt_hi, bt_lo
        sB[t][16] = 0u; sB[t][17] = 0u;
    }
    __syncthreads();

    // ---- precompute per-lane B fragments into smem (warp 0) ----
    if (wid == 0) {
        #pragma unroll
        for (int nt = 0; nt < 8; nt++) {
            const int row = 8 * nt + g;
            sFrag[nt][lane] = make_uint4(sB[row][c],     sB[row][4 + c],
                                         sB[row][8 + c], sB[row][12 + c]);
        }
    }
    __syncthreads();
    const float cv = sC[0];

    const int s16 = lane & 15;
    const bool hi_half = (lane >= 16);
    const int lm_sub = lane >> 3, lm_r = lane & 7;
    const int lm_row = lm_r + 8 * (lm_sub & 1);
    const uint32_t lm_base =
        (uint32_t)__cvta_generic_to_shared(&sA[wid][lm_row][0]) + (lm_sub >> 1) * 16;

    const int wglobal = blockIdx.x * 4 + wid;
    const int wstride = gridDim.x * 4;

    for (int ch = wglobal; ch < n_chunks; ch += wstride) {
        const int row = ch * 16 + s16;
        float xv[10];
        {
            const float2* p = (const float2*)(x + (size_t)row * 10);
            #pragma unroll
            for (int i = 0; i < 5; i++) { float2 v = p[i]; xv[2*i] = v.x; xv[2*i+1] = v.y; }
        }

        // envelope
        float env = fmaf(xv[0], xv[0], -1.f);
        #pragma unroll
        for (int d = 1; d < 10; d++) env *= fmaf(xv[d], xv[d], -1.f);
        env = env * rsqrtf(fmaf(env, env, 1000.f));

        // ---- branchless A staging ----
        uint32_t H[5], L[5];
        #pragma unroll
        for (int j = 0; j < 5; j++) {
            H[j] = bfpk(xv[2 * j], xv[2 * j + 1]);
            L[j] = bfpk(xv[2 * j] - bflo(H[j]), xv[2 * j + 1] - bfhi(H[j]));
        }
        const uint32_t w0 = hi_half ? L[3] : H[0];
        const uint32_t w1 = hi_half ? L[4] : H[1];
        const uint32_t w2 = hi_half ? H[0] : H[2];
        const uint32_t w3 = hi_half ? H[1] : H[3];
        const uint32_t w4 = hi_half ? H[2] : H[4];
        const uint32_t w5 = hi_half ? H[3] : L[0];
        const uint32_t w6 = hi_half ? H[4] : L[1];
        const uint32_t w7 = hi_half ? 0x3f803f80u : L[2];
        uint32_t* dst = &sA[wid][s16][(lane >> 4) << 3];
        *(uint4*)dst       = make_uint4(w0, w1, w2, w3);
        *(uint4*)(dst + 4) = make_uint4(w4, w5, w6, w7);
        __syncwarp();

        uint32_t a0[4], a1[4];
        asm volatile("ldmatrix.sync.aligned.m8n8.x4.shared.b16 {%0,%1,%2,%3}, [%4];"
                     : "=r"(a0[0]), "=r"(a0[1]), "=r"(a0[2]), "=r"(a0[3])
                     : "r"(lm_base));
        asm volatile("ldmatrix.sync.aligned.m8n8.x4.shared.b16 {%0,%1,%2,%3}, [%4];"
                     : "=r"(a1[0]), "=r"(a1[1]), "=r"(a1[2]), "=r"(a1[3])
                     : "r"(lm_base + 32));

        float accA = 0.f, accB = 0.f;
        #pragma unroll
        for (int nt = 0; nt < 8; nt++) {
            const uint4 bf = sFrag[nt][lane];
            float d0 = 0.f, d1 = 0.f, d2 = 0.f, d3 = 0.f;
            asm volatile(
                "mma.sync.aligned.m16n8k16.row.col.f32.bf16.bf16.f32 "
                "{%0,%1,%2,%3}, {%4,%5,%6,%7}, {%8,%9}, {%0,%1,%2,%3};"
                : "+f"(d0), "+f"(d1), "+f"(d2), "+f"(d3)
                : "r"(a0[0]), "r"(a0[1]), "r"(a0[2]), "r"(a0[3]),
                  "r"(bf.x), "r"(bf.y));
            asm volatile(
                "mma.sync.aligned.m16n8k16.row.col.f32.bf16.bf16.f32 "
                "{%0,%1,%2,%3}, {%4,%5,%6,%7}, {%8,%9}, {%0,%1,%2,%3};"
                : "+f"(d0), "+f"(d1), "+f"(d2), "+f"(d3)
                : "r"(a1[0]), "r"(a1[1]), "r"(a1[2]), "r"(a1[3]),
                  "r"(bf.z), "r"(bf.w));

            const float2 wv = *(const float2*)&sWeff[8 * nt + 2 * c];
            float s0, s1v, s2v, s3v;
            asm("sin.approx.f32 %0, %1;" : "=f"(s0)  : "f"(d0));
            asm("sin.approx.f32 %0, %1;" : "=f"(s1v) : "f"(d1));
            asm("sin.approx.f32 %0, %1;" : "=f"(s2v) : "f"(d2));
            asm("sin.approx.f32 %0, %1;" : "=f"(s3v) : "f"(d3));
            accA = fmaf(s0,  wv.x, accA);
            accA = fmaf(s1v, wv.y, accA);
            accB = fmaf(s2v, wv.x, accB);
            accB = fmaf(s3v, wv.y, accB);
        }

        // reduce over the 4 lanes (c=0..3) sharing the same sample rows
        accA += __shfl_xor_sync(0xffffffffu, accA, 1);
        accA += __shfl_xor_sync(0xffffffffu, accA, 2);
        accB += __shfl_xor_sync(0xffffffffu, accB, 1);
        accB += __shfl_xor_sync(0xffffffffu, accB, 2);

        const float envG  = __shfl_sync(0xffffffffu, env, g);
        const float envG8 = __shfl_sync(0xffffffffu, env, g + 8);

        const int base = ch * 16;
        if (c == 0 && base + g < N)     out[base + g]     = envG  * (accA + cv);
        if (c == 1 && base + g + 8 < N) out[base + g + 8] = envG8 * (accB + cv);
    }
}

// ---------------------------------------------------------------------------
extern "C" void kernel_launch(void* const* d_in, const int* in_sizes, int n_in,
                              void* d_out, int out_size) {
    const float* x     = (const float*)d_in[0];
    const float* Wt    = (const float*)d_in[1];
    const float* bt    = (const float*)d_in[2];
    const float* Wleaf = (const float*)d_in[3];
    const float* bleaf = (const float*)d_in[4];
    const float* W3    = (const float*)d_in[5];
    const float* b3    = (const float*)d_in[6];
    const float* W2    = (const float*)d_in[7];
    const float* b2    = (const float*)d_in[8];
    const float* W1    = (const float*)d_in[9];
    const float* b1    = (const float*)d_in[10];
    const float* Wr    = (const float*)d_in[11];
    const float* br    = (const float*)d_in[12];
    float* out = (float*)d_out;

    const int N = in_sizes[0] / 10;
    const int n_chunks = (N + 15) / 16;

    compose_kernel<<<16, 256>>>(Wleaf, bleaf, W3, b3, W2, b2, W1, b1, Wr, br);

    // exact fit: 1024 blocks x 4 warps x 4 chunks = 16384 chunks
    int grid = (n_chunks + 15) / 16;
    if (grid < 1) grid = 1;
    tree_main_kernel<<<grid, 128>>>(x, Wt, bt, out, N, n_chunks);
}